// round 6
// baseline (speedup 1.0000x reference)
#include <cuda_runtime.h>
#include <math.h>
#include <stdint.h>

// Problem constants
#define B_   4
#define S_   1024
#define E_   256
#define H_   32
#define DK_  8
#define NQ_  8
#define FF_  1024
#define M_   (B_ * S_)   // 4096

typedef unsigned long long ULL;

// ---------------- f32x2 packed math helpers (PTX-only on sm_103a) ----------
__device__ __forceinline__ ULL fma2(ULL a, ULL b, ULL c) {
    ULL d; asm("fma.rn.f32x2 %0, %1, %2, %3;" : "=l"(d) : "l"(a), "l"(b), "l"(c)); return d;
}
__device__ __forceinline__ ULL mul2(ULL a, ULL b) {
    ULL d; asm("mul.rn.f32x2 %0, %1, %2;" : "=l"(d) : "l"(a), "l"(b)); return d;
}
__device__ __forceinline__ ULL add2(ULL a, ULL b) {
    ULL d; asm("add.rn.f32x2 %0, %1, %2;" : "=l"(d) : "l"(a), "l"(b)); return d;
}
__device__ __forceinline__ ULL pk(float lo, float hi) {
    ULL r; asm("mov.b64 %0, {%1, %2};" : "=l"(r) : "f"(lo), "f"(hi)); return r;
}
__device__ __forceinline__ void unpk(ULL v, float& lo, float& hi) {
    asm("mov.b64 {%0, %1}, %2;" : "=f"(lo), "=f"(hi) : "l"(v));
}
__device__ __forceinline__ float ex2f_(float x) {
    float y; asm("ex2.approx.f32 %0, %1;" : "=f"(y) : "f"(x)); return y;
}

// ---------------- scratch (device globals; no runtime allocation) ----------
__device__ __align__(16) float g_qout[M_ * E_];
__device__ __align__(16) float g_qkv[M_ * 3 * E_];
__device__ __align__(16) float g_ctx[M_ * E_];
__device__ __align__(16) float g_Wf[E_ * E_];
__device__ __align__(16) float g_bf[E_];
__device__ __align__(16) float g_tmp[M_ * E_];
__device__ __align__(16) float g_h[M_ * E_];
__device__ __align__(16) float g_qf[M_ * NQ_];
__device__ __align__(16) ULL   g_w1p[FF_ / 2 * NQ_];   // packed w1 pairs: [gkp][j]
__device__ __align__(16) ULL   g_b1p[FF_ / 2];          // packed b1 pairs
// split-K attention partials (no-max softmax).
__device__ __align__(16) ULL g_pl[131072 * 2];
__device__ __align__(16) ULL g_pacc[(size_t)131072 * 16];

// ---------------- q_out = cos(x + theta[e % 8]), float4 --------------------
__global__ __launch_bounds__(256) void cos_encode_kernel(
    const float* __restrict__ x, const float* __restrict__ theta)
{
    int i = (blockIdx.x * 256 + threadIdx.x) * 4;
    float4 v = *(const float4*)(x + i);
    int j = i & 7;
    v.x = __cosf(v.x + theta[j + 0]);
    v.y = __cosf(v.y + theta[j + 1]);
    v.z = __cosf(v.z + theta[j + 2]);
    v.w = __cosf(v.w + theta[j + 3]);
    *(float4*)(g_qout + i) = v;
}

// ---------------- fold: Wf = w_comb @ w_out, bf = w_comb@b_out + b_comb -----
__global__ __launch_bounds__(256) void fold_w_kernel(
    const float* __restrict__ w_comb, const float* __restrict__ w_out,
    const float* __restrict__ b_out, const float* __restrict__ b_comb)
{
    int i = blockIdx.x;
    int j = threadIdx.x;
    float s = 0.f;
    #pragma unroll 8
    for (int k = 0; k < E_; k++)
        s = fmaf(w_comb[i * E_ + k], w_out[k * E_ + j], s);
    g_Wf[i * E_ + j] = s;

    __shared__ float red[256];
    red[j] = w_comb[i * E_ + j] * b_out[j];
    __syncthreads();
    #pragma unroll
    for (int off = 128; off > 0; off >>= 1) {
        if (j < off) red[j] += red[j + off];
        __syncthreads();
    }
    if (j == 0) g_bf[i] = red[0] + b_comb[i];
}

// ---------------- pack w1/b1 into duplicated-pair form ----------------------
__global__ __launch_bounds__(256) void pack_w1_kernel(
    const float* __restrict__ w1, const float* __restrict__ b1)
{
    int idx = blockIdx.x * 256 + threadIdx.x;
    if (idx < FF_ / 2 * NQ_) {
        int gkp = idx >> 3, j = idx & 7;
        g_w1p[idx] = pk(w1[gkp * 16 + j], w1[gkp * 16 + 8 + j]);
    } else if (idx < FF_ / 2 * NQ_ + FF_ / 2) {
        int i = idx - FF_ / 2 * NQ_;
        g_b1p[i] = pk(b1[2 * i], b1[2 * i + 1]);
    }
}

// ---------------- SGEMM 128x64x16, 128 threads, 8x8 microtile ---------------
// C[M,N] = A[M,K] @ Bw[N,K]^T + bias. M%128==0, N%64==0, K%16==0.
__global__ __launch_bounds__(128, 4) void sgemm128_kernel(
    const float* __restrict__ A, const float* __restrict__ Bw,
    const float* __restrict__ bias, float* __restrict__ C,
    int M, int N, int K)
{
    __shared__ float As[16][132];   // [k][m]
    __shared__ float Bs[16][68];    // [k][n]

    int t = threadIdx.x;
    int bm = blockIdx.y * 128;
    int bn = blockIdx.x * 64;
    int ty = t >> 3;                // 0..15 -> 8 m-rows
    int tx = t & 7;                 // 0..7  -> 8 n-cols
    int brow = t & 63;
    int bkoff = (t >> 6) * 8;

    const float* Aptr = A  + (size_t)(bm + t) * K;
    const float* Bptr = Bw + (size_t)(bn + brow) * K + bkoff;

    float4 a0 = *(const float4*)(Aptr);
    float4 a1 = *(const float4*)(Aptr + 4);
    float4 a2 = *(const float4*)(Aptr + 8);
    float4 a3 = *(const float4*)(Aptr + 12);
    float4 b0 = *(const float4*)(Bptr);
    float4 b1v = *(const float4*)(Bptr + 4);

    ULL acc[4][8];
    #pragma unroll
    for (int r = 0; r < 4; r++)
        #pragma unroll
        for (int n = 0; n < 8; n++) acc[r][n] = 0ULL;

    for (int k0 = 0; ; k0 += 16) {
        As[0][t] = a0.x;  As[1][t] = a0.y;  As[2][t] = a0.z;  As[3][t] = a0.w;
        As[4][t] = a1.x;  As[5][t] = a1.y;  As[6][t] = a1.z;  As[7][t] = a1.w;
        As[8][t] = a2.x;  As[9][t] = a2.y;  As[10][t] = a2.z; As[11][t] = a2.w;
        As[12][t] = a3.x; As[13][t] = a3.y; As[14][t] = a3.z; As[15][t] = a3.w;
        Bs[bkoff + 0][brow] = b0.x;  Bs[bkoff + 1][brow] = b0.y;
        Bs[bkoff + 2][brow] = b0.z;  Bs[bkoff + 3][brow] = b0.w;
        Bs[bkoff + 4][brow] = b1v.x; Bs[bkoff + 5][brow] = b1v.y;
        Bs[bkoff + 6][brow] = b1v.z; Bs[bkoff + 7][brow] = b1v.w;
        __syncthreads();

        bool last = (k0 + 16 >= K);
        if (!last) {
            Aptr += 16; Bptr += 16;
            a0 = *(const float4*)(Aptr);
            a1 = *(const float4*)(Aptr + 4);
            a2 = *(const float4*)(Aptr + 8);
            a3 = *(const float4*)(Aptr + 12);
            b0 = *(const float4*)(Bptr);
            b1v = *(const float4*)(Bptr + 4);
        }

        #pragma unroll
        for (int kk = 0; kk < 16; kk++) {
            ulonglong2 am0 = *(const ulonglong2*)&As[kk][ty * 8];
            ulonglong2 am1 = *(const ulonglong2*)&As[kk][ty * 8 + 4];
            float4 c0 = *(const float4*)&Bs[kk][tx * 8];
            float4 c1 = *(const float4*)&Bs[kk][tx * 8 + 4];
            ULL bb[8];
            bb[0] = pk(c0.x, c0.x); bb[1] = pk(c0.y, c0.y);
            bb[2] = pk(c0.z, c0.z); bb[3] = pk(c0.w, c0.w);
            bb[4] = pk(c1.x, c1.x); bb[5] = pk(c1.y, c1.y);
            bb[6] = pk(c1.z, c1.z); bb[7] = pk(c1.w, c1.w);
            ULL am[4] = {am0.x, am0.y, am1.x, am1.y};
            #pragma unroll
            for (int r = 0; r < 4; r++)
                #pragma unroll
                for (int n = 0; n < 8; n++)
                    acc[r][n] = fma2(am[r], bb[n], acc[r][n]);
        }
        if (last) break;
        __syncthreads();
    }

    int col = bn + tx * 8;
    float4 bi0 = *(const float4*)(bias + col);
    float4 bi1 = *(const float4*)(bias + col + 4);
    #pragma unroll
    for (int r = 0; r < 4; r++) {
        float lo[8], hi[8];
        #pragma unroll
        for (int n = 0; n < 8; n++) unpk(acc[r][n], lo[n], hi[n]);
        int row0 = bm + ty * 8 + 2 * r;
        float* c0p = C + (size_t)row0 * N + col;
        float* c1p = C + (size_t)(row0 + 1) * N + col;
        *(float4*)(c0p)     = make_float4(lo[0] + bi0.x, lo[1] + bi0.y, lo[2] + bi0.z, lo[3] + bi0.w);
        *(float4*)(c0p + 4) = make_float4(lo[4] + bi1.x, lo[5] + bi1.y, lo[6] + bi1.z, lo[7] + bi1.w);
        *(float4*)(c1p)     = make_float4(hi[0] + bi0.x, hi[1] + bi0.y, hi[2] + bi0.z, hi[3] + bi0.w);
        *(float4*)(c1p + 4) = make_float4(hi[4] + bi1.x, hi[5] + bi1.y, hi[6] + bi1.z, hi[7] + bi1.w);
    }
}

// ---------------- fused FFN GEMM: C = relu(qf@W1^T + b1) @ w2^T + b2 --------
// A-tile (hidden) generated in-kernel from g_qf (regs) + g_w1p/g_b1p (L1).
__global__ __launch_bounds__(128, 4) void sgemm_ffn_kernel(
    const float* __restrict__ w2, const float* __restrict__ b2,
    float* __restrict__ C)
{
    __shared__ float As[16][132];
    __shared__ float Bs[16][68];

    int t = threadIdx.x;
    int bm = blockIdx.y * 128;
    int bn = blockIdx.x * 64;
    int ty = t >> 3;
    int tx = t & 7;
    int brow = t & 63;
    int bkoff = (t >> 6) * 8;

    ULL qfd[8];
    {
        const float4* qp = (const float4*)(g_qf + (size_t)(bm + t) * NQ_);
        float4 q0 = qp[0], q1 = qp[1];
        qfd[0] = pk(q0.x, q0.x); qfd[1] = pk(q0.y, q0.y);
        qfd[2] = pk(q0.z, q0.z); qfd[3] = pk(q0.w, q0.w);
        qfd[4] = pk(q1.x, q1.x); qfd[5] = pk(q1.y, q1.y);
        qfd[6] = pk(q1.z, q1.z); qfd[7] = pk(q1.w, q1.w);
    }

    const float* Bptr = w2 + (size_t)(bn + brow) * FF_ + bkoff;
    float4 b0 = *(const float4*)(Bptr);
    float4 b1v = *(const float4*)(Bptr + 4);

    ULL acc[4][8];
    #pragma unroll
    for (int r = 0; r < 4; r++)
        #pragma unroll
        for (int n = 0; n < 8; n++) acc[r][n] = 0ULL;

    for (int k0 = 0; ; k0 += 16) {
        Bs[bkoff + 0][brow] = b0.x;  Bs[bkoff + 1][brow] = b0.y;
        Bs[bkoff + 2][brow] = b0.z;  Bs[bkoff + 3][brow] = b0.w;
        Bs[bkoff + 4][brow] = b1v.x; Bs[bkoff + 5][brow] = b1v.y;
        Bs[bkoff + 6][brow] = b1v.z; Bs[bkoff + 7][brow] = b1v.w;

        // generate hidden A-tile: rows bm+t, ff = k0..k0+15
        {
            int kpb = k0 >> 1;
            #pragma unroll
            for (int kp = 0; kp < 8; kp++) {
                const ulonglong2* wp = (const ulonglong2*)(g_w1p + (size_t)(kpb + kp) * 8);
                ulonglong2 w01 = wp[0], w23 = wp[1], w45 = wp[2], w67 = wp[3];
                ULL a2 = g_b1p[kpb + kp];
                a2 = fma2(qfd[0], w01.x, a2);
                a2 = fma2(qfd[1], w01.y, a2);
                a2 = fma2(qfd[2], w23.x, a2);
                a2 = fma2(qfd[3], w23.y, a2);
                a2 = fma2(qfd[4], w45.x, a2);
                a2 = fma2(qfd[5], w45.y, a2);
                a2 = fma2(qfd[6], w67.x, a2);
                a2 = fma2(qfd[7], w67.y, a2);
                float h0, h1;
                unpk(a2, h0, h1);
                As[2 * kp][t]     = fmaxf(h0, 0.f);
                As[2 * kp + 1][t] = fmaxf(h1, 0.f);
            }
        }
        __syncthreads();

        bool last = (k0 + 16 >= FF_);
        if (!last) {
            Bptr += 16;
            b0 = *(const float4*)(Bptr);
            b1v = *(const float4*)(Bptr + 4);
        }

        #pragma unroll
        for (int kk = 0; kk < 16; kk++) {
            ulonglong2 am0 = *(const ulonglong2*)&As[kk][ty * 8];
            ulonglong2 am1 = *(const ulonglong2*)&As[kk][ty * 8 + 4];
            float4 c0 = *(const float4*)&Bs[kk][tx * 8];
            float4 c1 = *(const float4*)&Bs[kk][tx * 8 + 4];
            ULL bb[8];
            bb[0] = pk(c0.x, c0.x); bb[1] = pk(c0.y, c0.y);
            bb[2] = pk(c0.z, c0.z); bb[3] = pk(c0.w, c0.w);
            bb[4] = pk(c1.x, c1.x); bb[5] = pk(c1.y, c1.y);
            bb[6] = pk(c1.z, c1.z); bb[7] = pk(c1.w, c1.w);
            ULL am[4] = {am0.x, am0.y, am1.x, am1.y};
            #pragma unroll
            for (int r = 0; r < 4; r++)
                #pragma unroll
                for (int n = 0; n < 8; n++)
                    acc[r][n] = fma2(am[r], bb[n], acc[r][n]);
        }
        if (last) break;
        __syncthreads();
    }

    int col = bn + tx * 8;
    float4 bi0 = *(const float4*)(b2 + col);
    float4 bi1 = *(const float4*)(b2 + col + 4);
    #pragma unroll
    for (int r = 0; r < 4; r++) {
        float lo[8], hi[8];
        #pragma unroll
        for (int n = 0; n < 8; n++) unpk(acc[r][n], lo[n], hi[n]);
        int row0 = bm + ty * 8 + 2 * r;
        float* c0p = C + (size_t)row0 * E_ + col;
        float* c1p = C + (size_t)(row0 + 1) * E_ + col;
        *(float4*)(c0p)     = make_float4(lo[0] + bi0.x, lo[1] + bi0.y, lo[2] + bi0.z, lo[3] + bi0.w);
        *(float4*)(c0p + 4) = make_float4(lo[4] + bi1.x, lo[5] + bi1.y, lo[6] + bi1.z, lo[7] + bi1.w);
        *(float4*)(c1p)     = make_float4(hi[0] + bi0.x, hi[1] + bi0.y, hi[2] + bi0.z, hi[3] + bi0.w);
        *(float4*)(c1p + 4) = make_float4(hi[4] + bi1.x, hi[5] + bi1.y, hi[6] + bi1.z, hi[7] + bi1.w);
    }
}

// ---------------- attention pass 1: split-K, no-max softmax, 4 q/thread -----
__global__ __launch_bounds__(128) void attn_p1_kernel()
{
    __shared__ ULL Kd[256 * 8];
    __shared__ ULL Vd[256 * 8];

    int kq = blockIdx.x;
    int qh = blockIdx.y;
    int bh = blockIdx.z;
    int b = bh >> 5;
    int h = bh & 31;
    int t = threadIdx.x;
    const float* base = g_qkv + (size_t)b * S_ * (3 * E_) + h * DK_;

    #pragma unroll
    for (int rep = 0; rep < 2; rep++) {
        int sk = rep * 128 + t;
        const float* rowp = base + (size_t)(kq * 256 + sk) * (3 * E_);
        float4 k0 = *(const float4*)(rowp + E_);
        float4 k1 = *(const float4*)(rowp + E_ + 4);
        float4 v0 = *(const float4*)(rowp + 2 * E_);
        float4 v1 = *(const float4*)(rowp + 2 * E_ + 4);
        ulonglong2* kr = (ulonglong2*)(Kd + sk * 8);
        ulonglong2* vr = (ulonglong2*)(Vd + sk * 8);
        kr[0] = make_ulonglong2(pk(k0.x, k0.x), pk(k0.y, k0.y));
        kr[1] = make_ulonglong2(pk(k0.z, k0.z), pk(k0.w, k0.w));
        kr[2] = make_ulonglong2(pk(k1.x, k1.x), pk(k1.y, k1.y));
        kr[3] = make_ulonglong2(pk(k1.z, k1.z), pk(k1.w, k1.w));
        vr[0] = make_ulonglong2(pk(v0.x, v0.x), pk(v0.y, v0.y));
        vr[1] = make_ulonglong2(pk(v0.z, v0.z), pk(v0.w, v0.w));
        vr[2] = make_ulonglong2(pk(v1.x, v1.x), pk(v1.y, v1.y));
        vr[3] = make_ulonglong2(pk(v1.z, v1.z), pk(v1.w, v1.w));
    }
    __syncthreads();

    const float qscale = 0.35355339059327373f * 1.4426950408889634f;

    ULL qA[8], qB[8];
    {
        const float* r0 = base + (size_t)(qh * 512 + t)       * (3 * E_);
        const float* r1 = base + (size_t)(qh * 512 + t + 128) * (3 * E_);
        const float* r2 = base + (size_t)(qh * 512 + t + 256) * (3 * E_);
        const float* r3 = base + (size_t)(qh * 512 + t + 384) * (3 * E_);
        float4 a0 = *(const float4*)(r0), a1 = *(const float4*)(r0 + 4);
        float4 b0 = *(const float4*)(r1), b1 = *(const float4*)(r1 + 4);
        float4 c0 = *(const float4*)(r2), c1 = *(const float4*)(r2 + 4);
        float4 d0 = *(const float4*)(r3), d1 = *(const float4*)(r3 + 4);
        qA[0] = pk(a0.x * qscale, b0.x * qscale);
        qA[1] = pk(a0.y * qscale, b0.y * qscale);
        qA[2] = pk(a0.z * qscale, b0.z * qscale);
        qA[3] = pk(a0.w * qscale, b0.w * qscale);
        qA[4] = pk(a1.x * qscale, b1.x * qscale);
        qA[5] = pk(a1.y * qscale, b1.y * qscale);
        qA[6] = pk(a1.z * qscale, b1.z * qscale);
        qA[7] = pk(a1.w * qscale, b1.w * qscale);
        qB[0] = pk(c0.x * qscale, d0.x * qscale);
        qB[1] = pk(c0.y * qscale, d0.y * qscale);
        qB[2] = pk(c0.z * qscale, d0.z * qscale);
        qB[3] = pk(c0.w * qscale, d0.w * qscale);
        qB[4] = pk(c1.x * qscale, d1.x * qscale);
        qB[5] = pk(c1.y * qscale, d1.y * qscale);
        qB[6] = pk(c1.z * qscale, d1.z * qscale);
        qB[7] = pk(c1.w * qscale, d1.w * qscale);
    }

    ULL lA = 0ULL, lB = 0ULL;
    ULL accA[8], accB[8];
    #pragma unroll
    for (int c = 0; c < 8; c++) { accA[c] = 0ULL; accB[c] = 0ULL; }

    #pragma unroll 2
    for (int s = 0; s < 256; s++) {
        const ulonglong2* kr = (const ulonglong2*)(Kd + s * 8);
        ulonglong2 k01 = kr[0], k23 = kr[1], k45 = kr[2], k67 = kr[3];

        ULL tA = mul2(qA[0], k01.x);
        ULL tB = mul2(qB[0], k01.x);
        tA = fma2(qA[1], k01.y, tA);
        tB = fma2(qB[1], k01.y, tB);
        tA = fma2(qA[2], k23.x, tA);
        tB = fma2(qB[2], k23.x, tB);
        tA = fma2(qA[3], k23.y, tA);
        tB = fma2(qB[3], k23.y, tB);
        tA = fma2(qA[4], k45.x, tA);
        tB = fma2(qB[4], k45.x, tB);
        tA = fma2(qA[5], k45.y, tA);
        tB = fma2(qB[5], k45.y, tB);
        tA = fma2(qA[6], k67.x, tA);
        tB = fma2(qB[6], k67.x, tB);
        tA = fma2(qA[7], k67.y, tA);
        tB = fma2(qB[7], k67.y, tB);

        float dA0, dA1, dB0, dB1;
        unpk(tA, dA0, dA1);
        unpk(tB, dB0, dB1);
        ULL ppA = pk(ex2f_(dA0), ex2f_(dA1));
        ULL ppB = pk(ex2f_(dB0), ex2f_(dB1));
        lA = add2(lA, ppA);
        lB = add2(lB, ppB);

        const ulonglong2* vr = (const ulonglong2*)(Vd + s * 8);
        ulonglong2 v01 = vr[0], v23 = vr[1], v45 = vr[2], v67 = vr[3];
        accA[0] = fma2(ppA, v01.x, accA[0]);
        accB[0] = fma2(ppB, v01.x, accB[0]);
        accA[1] = fma2(ppA, v01.y, accA[1]);
        accB[1] = fma2(ppB, v01.y, accB[1]);
        accA[2] = fma2(ppA, v23.x, accA[2]);
        accB[2] = fma2(ppB, v23.x, accB[2]);
        accA[3] = fma2(ppA, v23.y, accA[3]);
        accB[3] = fma2(ppB, v23.y, accB[3]);
        accA[4] = fma2(ppA, v45.x, accA[4]);
        accB[4] = fma2(ppB, v45.x, accB[4]);
        accA[5] = fma2(ppA, v45.y, accA[5]);
        accB[5] = fma2(ppB, v45.y, accB[5]);
        accA[6] = fma2(ppA, v67.x, accA[6]);
        accB[6] = fma2(ppB, v67.x, accB[6]);
        accA[7] = fma2(ppA, v67.y, accA[7]);
        accB[7] = fma2(ppB, v67.y, accB[7]);
    }

    int pidx = ((bh * 4 + kq) * 2 + qh) * 128 + t;
    ((ulonglong2*)g_pl)[pidx] = make_ulonglong2(lA, lB);
    ulonglong2* pa = (ulonglong2*)(g_pacc + (size_t)pidx * 16);
    pa[0] = make_ulonglong2(accA[0], accA[1]);
    pa[1] = make_ulonglong2(accA[2], accA[3]);
    pa[2] = make_ulonglong2(accA[4], accA[5]);
    pa[3] = make_ulonglong2(accA[6], accA[7]);
    pa[4] = make_ulonglong2(accB[0], accB[1]);
    pa[5] = make_ulonglong2(accB[2], accB[3]);
    pa[6] = make_ulonglong2(accB[4], accB[5]);
    pa[7] = make_ulonglong2(accB[6], accB[7]);
}

// ---------------- attention pass 2: sum 4 partials, normalize ---------------
__global__ __launch_bounds__(256) void attn_p2_kernel()
{
    int idx = blockIdx.x * 256 + threadIdx.x;
    int bh = idx >> 8;
    int r  = idx & 255;
    int qh = r >> 7;
    int t  = r & 127;
    int b = bh >> 5;
    int h = bh & 31;

    ULL lA = 0ULL, lB = 0ULL;
    ULL cA[8], cB[8];
    #pragma unroll
    for (int j = 0; j < 8; j++) { cA[j] = 0ULL; cB[j] = 0ULL; }

    #pragma unroll
    for (int kq = 0; kq < 4; kq++) {
        int pidx = ((bh * 4 + kq) * 2 + qh) * 128 + t;
        ulonglong2 lp = ((const ulonglong2*)g_pl)[pidx];
        lA = add2(lA, lp.x);
        lB = add2(lB, lp.y);
        const ulonglong2* pa = (const ulonglong2*)(g_pacc + (size_t)pidx * 16);
        ulonglong2 a0 = pa[0], a1 = pa[1], a2 = pa[2], a3 = pa[3];
        ulonglong2 b0 = pa[4], b1 = pa[5], b2 = pa[6], b3 = pa[7];
        cA[0] = add2(cA[0], a0.x); cA[1] = add2(cA[1], a0.y);
        cA[2] = add2(cA[2], a1.x); cA[3] = add2(cA[3], a1.y);
        cA[4] = add2(cA[4], a2.x); cA[5] = add2(cA[5], a2.y);
        cA[6] = add2(cA[6], a3.x); cA[7] = add2(cA[7], a3.y);
        cB[0] = add2(cB[0], b0.x); cB[1] = add2(cB[1], b0.y);
        cB[2] = add2(cB[2], b1.x); cB[3] = add2(cB[3], b1.y);
        cB[4] = add2(cB[4], b2.x); cB[5] = add2(cB[5], b2.y);
        cB[6] = add2(cB[6], b3.x); cB[7] = add2(cB[7], b3.y);
    }

    float LA0, LA1, LB0, LB1;
    unpk(lA, LA0, LA1);
    unpk(lB, LB0, LB1);
    float r0 = 1.f / LA0, r1 = 1.f / LA1, r2 = 1.f / LB0, r3 = 1.f / LB1;

    int q0 = qh * 512 + t;
    float* o0 = g_ctx + ((size_t)b * S_ + q0)       * E_ + h * DK_;
    float* o1 = g_ctx + ((size_t)b * S_ + q0 + 128) * E_ + h * DK_;
    float* o2 = g_ctx + ((size_t)b * S_ + q0 + 256) * E_ + h * DK_;
    float* o3 = g_ctx + ((size_t)b * S_ + q0 + 384) * E_ + h * DK_;

    float xA0[8], xA1[8], xB0[8], xB1[8];
    #pragma unroll
    for (int j = 0; j < 8; j++) { unpk(cA[j], xA0[j], xA1[j]); unpk(cB[j], xB0[j], xB1[j]); }
    float4 w;
    w.x = xA0[0]*r0; w.y = xA0[1]*r0; w.z = xA0[2]*r0; w.w = xA0[3]*r0;
    *(float4*)(o0) = w;
    w.x = xA0[4]*r0; w.y = xA0[5]*r0; w.z = xA0[6]*r0; w.w = xA0[7]*r0;
    *(float4*)(o0 + 4) = w;
    w.x = xA1[0]*r1; w.y = xA1[1]*r1; w.z = xA1[2]*r1; w.w = xA1[3]*r1;
    *(float4*)(o1) = w;
    w.x = xA1[4]*r1; w.y = xA1[5]*r1; w.z = xA1[6]*r1; w.w = xA1[7]*r1;
    *(float4*)(o1 + 4) = w;
    w.x = xB0[0]*r2; w.y = xB0[1]*r2; w.z = xB0[2]*r2; w.w = xB0[3]*r2;
    *(float4*)(o2) = w;
    w.x = xB0[4]*r2; w.y = xB0[5]*r2; w.z = xB0[6]*r2; w.w = xB0[7]*r2;
    *(float4*)(o2 + 4) = w;
    w.x = xB1[0]*r3; w.y = xB1[1]*r3; w.z = xB1[2]*r3; w.w = xB1[3]*r3;
    *(float4*)(o3) = w;
    w.x = xB1[4]*r3; w.y = xB1[5]*r3; w.z = xB1[6]*r3; w.w = xB1[7]*r3;
    *(float4*)(o3 + 4) = w;
}

// ---------------- layernorm: out = LN(a + b) * g + beta  (warp per row) -----
__global__ __launch_bounds__(256) void ln_kernel(
    const float* __restrict__ a, const float* __restrict__ bsrc,
    const float* __restrict__ g, const float* __restrict__ beta,
    float* __restrict__ out)
{
    int row  = (blockIdx.x * 256 + threadIdx.x) >> 5;
    int lane = threadIdx.x & 31;
    size_t off = (size_t)row * E_ + lane * 8;

    const float4* ap = (const float4*)(a + off);
    const float4* bp = (const float4*)(bsrc + off);
    float4 a0 = ap[0], a1 = ap[1], b0 = bp[0], b1 = bp[1];
    float v[8];
    v[0] = a0.x + b0.x; v[1] = a0.y + b0.y; v[2] = a0.z + b0.z; v[3] = a0.w + b0.w;
    v[4] = a1.x + b1.x; v[5] = a1.y + b1.y; v[6] = a1.z + b1.z; v[7] = a1.w + b1.w;

    float s = 0.f, ss = 0.f;
    #pragma unroll
    for (int i = 0; i < 8; i++) { s += v[i]; ss = fmaf(v[i], v[i], ss); }
    #pragma unroll
    for (int o = 16; o > 0; o >>= 1) {
        s  += __shfl_xor_sync(0xFFFFFFFFu, s,  o);
        ss += __shfl_xor_sync(0xFFFFFFFFu, ss, o);
    }
    float mu  = s * (1.f / E_);
    float var = ss * (1.f / E_) - mu * mu;
    float rs  = rsqrtf(var + 1e-5f);

    const float4* gp  = (const float4*)(g    + lane * 8);
    const float4* bep = (const float4*)(beta + lane * 8);
    float4 g0 = gp[0], g1v = gp[1], e0 = bep[0], e1 = bep[1];

    float4 w;
    w.x = (v[0]-mu)*rs*g0.x + e0.x; w.y = (v[1]-mu)*rs*g0.y + e0.y;
    w.z = (v[2]-mu)*rs*g0.z + e0.z; w.w = (v[3]-mu)*rs*g0.w + e0.w;
    *(float4*)(out + off) = w;
    w.x = (v[4]-mu)*rs*g1v.x + e1.x; w.y = (v[5]-mu)*rs*g1v.y + e1.y;
    w.z = (v[6]-mu)*rs*g1v.z + e1.z; w.w = (v[7]-mu)*rs*g1v.w + e1.w;
    *(float4*)(out + off + 4) = w;
}

// ---------------- qf = cos(theta)*cos(h @ w_ip^T + b_ip), warp per row ------
// lane = j*4 + p: thread handles output j, quarter p of the K=256 reduction.
__global__ __launch_bounds__(256) void qf_kernel(
    const float* __restrict__ w_ip, const float* __restrict__ b_ip,
    const float* __restrict__ theta_ffn)
{
    int tid = threadIdx.x;
    int m = blockIdx.x * 8 + (tid >> 5);
    int lane = tid & 31;
    int j = lane >> 2, p = lane & 3;
    const float* hr = g_h + (size_t)m * E_ + p * 64;
    const float* wr = w_ip + (size_t)j * E_ + p * 64;
    ULL acc = 0ULL;
    #pragma unroll
    for (int i = 0; i < 64; i += 8) {
        float4 hA = *(const float4*)(hr + i);
        float4 hB = *(const float4*)(hr + i + 4);
        float4 wA = *(const float4*)(wr + i);
        float4 wB = *(const float4*)(wr + i + 4);
        acc = fma2(pk(hA.x, hA.y), pk(wA.x, wA.y), acc);
        acc = fma2(pk(hA.z, hA.w), pk(wA.z, wA.w), acc);
        acc = fma2(pk(hB.x, hB.y), pk(wB.x, wB.y), acc);
        acc = fma2(pk(hB.z, hB.w), pk(wB.z, wB.w), acc);
    }
    float s0, s1;
    unpk(acc, s0, s1);
    float s = s0 + s1;
    s += __shfl_xor_sync(0xFFFFFFFFu, s, 1);
    s += __shfl_xor_sync(0xFFFFFFFFu, s, 2);
    if (p == 0)
        g_qf[m * NQ_ + j] = __cosf(theta_ffn[j]) * __cosf(s + b_ip[j]);
}

// ---------------- launch ----------------------------------------------------
extern "C" void kernel_launch(void* const* d_in, const int* in_sizes, int n_in,
                              void* d_out, int out_size)
{
    (void)in_sizes; (void)n_in; (void)out_size;

    const float* x          = (const float*)d_in[0];
    const float* theta_attn = (const float*)d_in[1];
    const float* w_in       = (const float*)d_in[2];
    const float* b_in       = (const float*)d_in[3];
    const float* w_out      = (const float*)d_in[4];
    const float* b_out      = (const float*)d_in[5];
    const float* w_comb     = (const float*)d_in[6];
    const float* b_comb     = (const float*)d_in[7];
    const float* g1         = (const float*)d_in[8];
    const float* be1        = (const float*)d_in[9];
    const float* g2         = (const float*)d_in[10];
    const float* be2        = (const float*)d_in[11];
    const float* w_ip       = (const float*)d_in[12];
    const float* b_ip       = (const float*)d_in[13];
    const float* theta_ffn  = (const float*)d_in[14];
    const float* w1         = (const float*)d_in[15];
    const float* b1         = (const float*)d_in[16];
    const float* w2         = (const float*)d_in[17];
    const float* b2         = (const float*)d_in[18];
    float* out = (float*)d_out;

    float *p_qout, *p_qkv, *p_ctx, *p_Wf, *p_bf, *p_tmp, *p_h;
    cudaGetSymbolAddress((void**)&p_qout, g_qout);
    cudaGetSymbolAddress((void**)&p_qkv,  g_qkv);
    cudaGetSymbolAddress((void**)&p_ctx,  g_ctx);
    cudaGetSymbolAddress((void**)&p_Wf,   g_Wf);
    cudaGetSymbolAddress((void**)&p_bf,   g_bf);
    cudaGetSymbolAddress((void**)&p_tmp,  g_tmp);
    cudaGetSymbolAddress((void**)&p_h,    g_h);

    // 1. q_out = cos(x + theta)
    cos_encode_kernel<<<(M_ * E_) / 1024, 256>>>(x, theta_attn);

    // 2. fold w_comb @ w_out ; pack w1/b1 pairs
    fold_w_kernel<<<E_, 256>>>(w_comb, w_out, b_out, b_comb);
    pack_w1_kernel<<<18, 256>>>(w1, b1);

    // 3. qkv = q_out @ w_in^T + b_in      [4096 x 768]
    {
        dim3 grid((3 * E_) / 64, M_ / 128);
        sgemm128_kernel<<<grid, 128>>>(p_qout, w_in, b_in, p_qkv, M_, 3 * E_, E_);
    }

    // 4a. attention pass 1 (split-K partials)
    {
        dim3 grid(4, 2, B_ * H_);
        attn_p1_kernel<<<grid, 128>>>();
    }
    // 4b. attention pass 2 (sum + normalize) -> ctx
    attn_p2_kernel<<<128, 256>>>();

    // 5. attn_out = ctx @ Wf^T + bf       [4096 x 256]
    {
        dim3 grid(E_ / 64, M_ / 128);
        sgemm128_kernel<<<grid, 128>>>(p_ctx, p_Wf, p_bf, p_tmp, M_, E_, E_);
    }

    // 6. h = LN(x + attn_out) * g1 + be1
    ln_kernel<<<M_ / 8, 256>>>(x, p_tmp, g1, be1, p_h);

    // 7. qf = cos(theta_ffn) * cos(h @ w_ip^T + b_ip)
    qf_kernel<<<M_ / 8, 256>>>(w_ip, b_ip, theta_ffn);

    // 8+9. ffn_out = relu(qf @ w1^T + b1) @ w2^T + b2   (fused)
    {
        dim3 grid(E_ / 64, M_ / 128);
        sgemm_ffn_kernel<<<grid, 128>>>(w2, b2, p_tmp);
    }

    // 10. out = LN(h + ffn_out) * g2 + be2
    ln_kernel<<<M_ / 8, 256>>>(p_h, p_tmp, g2, be2, out);
}

// round 7
// speedup vs baseline: 1.0958x; 1.0958x over previous
#include <cuda_runtime.h>
#include <math.h>
#include <stdint.h>

// Problem constants
#define B_   4
#define S_   1024
#define E_   256
#define H_   32
#define DK_  8
#define NQ_  8
#define FF_  1024
#define M_   (B_ * S_)   // 4096

typedef unsigned long long ULL;

// ---------------- f32x2 packed math helpers (PTX-only on sm_103a) ----------
__device__ __forceinline__ ULL fma2(ULL a, ULL b, ULL c) {
    ULL d; asm("fma.rn.f32x2 %0, %1, %2, %3;" : "=l"(d) : "l"(a), "l"(b), "l"(c)); return d;
}
__device__ __forceinline__ ULL mul2(ULL a, ULL b) {
    ULL d; asm("mul.rn.f32x2 %0, %1, %2;" : "=l"(d) : "l"(a), "l"(b)); return d;
}
__device__ __forceinline__ ULL add2(ULL a, ULL b) {
    ULL d; asm("add.rn.f32x2 %0, %1, %2;" : "=l"(d) : "l"(a), "l"(b)); return d;
}
__device__ __forceinline__ ULL pk(float lo, float hi) {
    ULL r; asm("mov.b64 %0, {%1, %2};" : "=l"(r) : "f"(lo), "f"(hi)); return r;
}
__device__ __forceinline__ void unpk(ULL v, float& lo, float& hi) {
    asm("mov.b64 {%0, %1}, %2;" : "=f"(lo), "=f"(hi) : "l"(v));
}
__device__ __forceinline__ float ex2f_(float x) {
    float y; asm("ex2.approx.f32 %0, %1;" : "=f"(y) : "f"(x)); return y;
}

// ---------------- scratch (device globals; no runtime allocation) ----------
__device__ __align__(16) float g_qout[M_ * E_];
__device__ __align__(16) float g_qkv[M_ * 3 * E_];
__device__ __align__(16) float g_ctx[M_ * E_];
__device__ __align__(16) float g_Wf[E_ * E_];
__device__ __align__(16) float g_bf[E_];
__device__ __align__(16) float g_tmp[M_ * E_];
__device__ __align__(16) float g_h[M_ * E_];
__device__ __align__(16) float g_qf[M_ * NQ_];
__device__ __align__(16) float g_hidden[M_ * FF_];
// split-K attention partials (no-max softmax).
__device__ __align__(16) ULL g_pl[131072 * 2];
__device__ __align__(16) ULL g_pacc[(size_t)131072 * 16];

// ---------------- q_out = cos(x + theta[e % 8]), float4 --------------------
__global__ __launch_bounds__(256) void cos_encode_kernel(
    const float* __restrict__ x, const float* __restrict__ theta)
{
    int i = (blockIdx.x * 256 + threadIdx.x) * 4;
    float4 v = *(const float4*)(x + i);
    int j = i & 7;
    v.x = __cosf(v.x + theta[j + 0]);
    v.y = __cosf(v.y + theta[j + 1]);
    v.z = __cosf(v.z + theta[j + 2]);
    v.w = __cosf(v.w + theta[j + 3]);
    *(float4*)(g_qout + i) = v;
}

// ---------------- fold: Wf = w_comb @ w_out, bf = w_comb@b_out + b_comb -----
__global__ __launch_bounds__(256) void fold_w_kernel(
    const float* __restrict__ w_comb, const float* __restrict__ w_out,
    const float* __restrict__ b_out, const float* __restrict__ b_comb)
{
    int i = blockIdx.x;
    int j = threadIdx.x;
    float s = 0.f;
    #pragma unroll 8
    for (int k = 0; k < E_; k++)
        s = fmaf(w_comb[i * E_ + k], w_out[k * E_ + j], s);
    g_Wf[i * E_ + j] = s;

    __shared__ float red[256];
    red[j] = w_comb[i * E_ + j] * b_out[j];
    __syncthreads();
    #pragma unroll
    for (int off = 128; off > 0; off >>= 1) {
        if (j < off) red[j] += red[j + off];
        __syncthreads();
    }
    if (j == 0) g_bf[i] = red[0] + b_comb[i];
}

// ---------------- SGEMM 64x64x16, 256 threads, (2 m-pair)x4 microtile -------
// C[M,N] = A[M,K] @ Bw[N,K]^T + bias. M%64==0, N%64==0, K%16==0.
// Small tile -> many CTAs -> latency hidden by other CTAs, pipe-bound inner loop.
__global__ __launch_bounds__(256) void sgemm64_kernel(
    const float* __restrict__ A, const float* __restrict__ Bw,
    const float* __restrict__ bias, float* __restrict__ C,
    int M, int N, int K)
{
    __shared__ float As[16][68];   // [k][m]
    __shared__ float Bs[16][68];   // [k][n]

    int tid = threadIdx.x;
    int bm = blockIdx.y * 64;
    int bn = blockIdx.x * 64;
    int lr = tid >> 2;             // 0..63 load row
    int lc = (tid & 3) * 4;        // 0,4,8,12 load k-offset
    int ty = tid >> 4;             // 0..15 -> 4 m-rows (2 packed pairs)
    int tx = tid & 15;             // 0..15 -> 4 n-cols

    const float* Aptr = A  + (size_t)(bm + lr) * K + lc;
    const float* Bptr = Bw + (size_t)(bn + lr) * K + lc;

    float4 a0 = *(const float4*)(Aptr);
    float4 b0 = *(const float4*)(Bptr);

    ULL acc[2][4];
    #pragma unroll
    for (int r = 0; r < 2; r++)
        #pragma unroll
        for (int n = 0; n < 4; n++) acc[r][n] = 0ULL;

    for (int k0 = 0; ; k0 += 16) {
        As[lc + 0][lr] = a0.x; As[lc + 1][lr] = a0.y;
        As[lc + 2][lr] = a0.z; As[lc + 3][lr] = a0.w;
        Bs[lc + 0][lr] = b0.x; Bs[lc + 1][lr] = b0.y;
        Bs[lc + 2][lr] = b0.z; Bs[lc + 3][lr] = b0.w;
        __syncthreads();

        bool last = (k0 + 16 >= K);
        if (!last) {
            Aptr += 16; Bptr += 16;
            a0 = *(const float4*)(Aptr);
            b0 = *(const float4*)(Bptr);
        }

        #pragma unroll
        for (int kk = 0; kk < 16; kk++) {
            ulonglong2 am = *(const ulonglong2*)&As[kk][ty * 4]; // (m0,m1),(m2,m3)
            float4 b4 = *(const float4*)&Bs[kk][tx * 4];
            ULL bb0 = pk(b4.x, b4.x), bb1 = pk(b4.y, b4.y);
            ULL bb2 = pk(b4.z, b4.z), bb3 = pk(b4.w, b4.w);
            acc[0][0] = fma2(am.x, bb0, acc[0][0]);
            acc[0][1] = fma2(am.x, bb1, acc[0][1]);
            acc[0][2] = fma2(am.x, bb2, acc[0][2]);
            acc[0][3] = fma2(am.x, bb3, acc[0][3]);
            acc[1][0] = fma2(am.y, bb0, acc[1][0]);
            acc[1][1] = fma2(am.y, bb1, acc[1][1]);
            acc[1][2] = fma2(am.y, bb2, acc[1][2]);
            acc[1][3] = fma2(am.y, bb3, acc[1][3]);
        }
        if (last) break;
        __syncthreads();
    }

    int col = bn + tx * 4;
    float4 bb = *(const float4*)(bias + col);
    #pragma unroll
    for (int r = 0; r < 2; r++) {
        float lo0, hi0, lo1, hi1, lo2v, hi2, lo3, hi3;
        unpk(acc[r][0], lo0, hi0);
        unpk(acc[r][1], lo1, hi1);
        unpk(acc[r][2], lo2v, hi2);
        unpk(acc[r][3], lo3, hi3);
        int row0 = bm + ty * 4 + 2 * r;
        *(float4*)(C + (size_t)row0 * N + col) =
            make_float4(lo0 + bb.x, lo1 + bb.y, lo2v + bb.z, lo3 + bb.w);
        *(float4*)(C + (size_t)(row0 + 1) * N + col) =
            make_float4(hi0 + bb.x, hi1 + bb.y, hi2 + bb.z, hi3 + bb.w);
    }
}

// ---------------- attention pass 1: split-K, no-max softmax, 4 q/thread -----
// grid = (4 key-quarters, 2 query-halves, 128 bh), 128 threads.
__global__ __launch_bounds__(128) void attn_p1_kernel()
{
    __shared__ ULL Kd[256 * 8];
    __shared__ ULL Vd[256 * 8];

    int kq = blockIdx.x;
    int qh = blockIdx.y;
    int bh = blockIdx.z;
    int b = bh >> 5;
    int h = bh & 31;
    int t = threadIdx.x;
    const float* base = g_qkv + (size_t)b * S_ * (3 * E_) + h * DK_;

    #pragma unroll
    for (int rep = 0; rep < 2; rep++) {
        int sk = rep * 128 + t;
        const float* rowp = base + (size_t)(kq * 256 + sk) * (3 * E_);
        float4 k0 = *(const float4*)(rowp + E_);
        float4 k1 = *(const float4*)(rowp + E_ + 4);
        float4 v0 = *(const float4*)(rowp + 2 * E_);
        float4 v1 = *(const float4*)(rowp + 2 * E_ + 4);
        ulonglong2* kr = (ulonglong2*)(Kd + sk * 8);
        ulonglong2* vr = (ulonglong2*)(Vd + sk * 8);
        kr[0] = make_ulonglong2(pk(k0.x, k0.x), pk(k0.y, k0.y));
        kr[1] = make_ulonglong2(pk(k0.z, k0.z), pk(k0.w, k0.w));
        kr[2] = make_ulonglong2(pk(k1.x, k1.x), pk(k1.y, k1.y));
        kr[3] = make_ulonglong2(pk(k1.z, k1.z), pk(k1.w, k1.w));
        vr[0] = make_ulonglong2(pk(v0.x, v0.x), pk(v0.y, v0.y));
        vr[1] = make_ulonglong2(pk(v0.z, v0.z), pk(v0.w, v0.w));
        vr[2] = make_ulonglong2(pk(v1.x, v1.x), pk(v1.y, v1.y));
        vr[3] = make_ulonglong2(pk(v1.z, v1.z), pk(v1.w, v1.w));
    }
    __syncthreads();

    const float qscale = 0.35355339059327373f * 1.4426950408889634f;

    ULL qA[8], qB[8];
    {
        const float* r0 = base + (size_t)(qh * 512 + t)       * (3 * E_);
        const float* r1 = base + (size_t)(qh * 512 + t + 128) * (3 * E_);
        const float* r2 = base + (size_t)(qh * 512 + t + 256) * (3 * E_);
        const float* r3 = base + (size_t)(qh * 512 + t + 384) * (3 * E_);
        float4 a0 = *(const float4*)(r0), a1 = *(const float4*)(r0 + 4);
        float4 b0 = *(const float4*)(r1), b1 = *(const float4*)(r1 + 4);
        float4 c0 = *(const float4*)(r2), c1 = *(const float4*)(r2 + 4);
        float4 d0 = *(const float4*)(r3), d1 = *(const float4*)(r3 + 4);
        qA[0] = pk(a0.x * qscale, b0.x * qscale);
        qA[1] = pk(a0.y * qscale, b0.y * qscale);
        qA[2] = pk(a0.z * qscale, b0.z * qscale);
        qA[3] = pk(a0.w * qscale, b0.w * qscale);
        qA[4] = pk(a1.x * qscale, b1.x * qscale);
        qA[5] = pk(a1.y * qscale, b1.y * qscale);
        qA[6] = pk(a1.z * qscale, b1.z * qscale);
        qA[7] = pk(a1.w * qscale, b1.w * qscale);
        qB[0] = pk(c0.x * qscale, d0.x * qscale);
        qB[1] = pk(c0.y * qscale, d0.y * qscale);
        qB[2] = pk(c0.z * qscale, d0.z * qscale);
        qB[3] = pk(c0.w * qscale, d0.w * qscale);
        qB[4] = pk(c1.x * qscale, d1.x * qscale);
        qB[5] = pk(c1.y * qscale, d1.y * qscale);
        qB[6] = pk(c1.z * qscale, d1.z * qscale);
        qB[7] = pk(c1.w * qscale, d1.w * qscale);
    }

    ULL lA = 0ULL, lB = 0ULL;
    ULL accA[8], accB[8];
    #pragma unroll
    for (int c = 0; c < 8; c++) { accA[c] = 0ULL; accB[c] = 0ULL; }

    #pragma unroll 2
    for (int s = 0; s < 256; s++) {
        const ulonglong2* kr = (const ulonglong2*)(Kd + s * 8);
        ulonglong2 k01 = kr[0], k23 = kr[1], k45 = kr[2], k67 = kr[3];

        ULL tA = mul2(qA[0], k01.x);
        ULL tB = mul2(qB[0], k01.x);
        tA = fma2(qA[1], k01.y, tA);
        tB = fma2(qB[1], k01.y, tB);
        tA = fma2(qA[2], k23.x, tA);
        tB = fma2(qB[2], k23.x, tB);
        tA = fma2(qA[3], k23.y, tA);
        tB = fma2(qB[3], k23.y, tB);
        tA = fma2(qA[4], k45.x, tA);
        tB = fma2(qB[4], k45.x, tB);
        tA = fma2(qA[5], k45.y, tA);
        tB = fma2(qB[5], k45.y, tB);
        tA = fma2(qA[6], k67.x, tA);
        tB = fma2(qB[6], k67.x, tB);
        tA = fma2(qA[7], k67.y, tA);
        tB = fma2(qB[7], k67.y, tB);

        float dA0, dA1, dB0, dB1;
        unpk(tA, dA0, dA1);
        unpk(tB, dB0, dB1);
        ULL ppA = pk(ex2f_(dA0), ex2f_(dA1));
        ULL ppB = pk(ex2f_(dB0), ex2f_(dB1));
        lA = add2(lA, ppA);
        lB = add2(lB, ppB);

        const ulonglong2* vr = (const ulonglong2*)(Vd + s * 8);
        ulonglong2 v01 = vr[0], v23 = vr[1], v45 = vr[2], v67 = vr[3];
        accA[0] = fma2(ppA, v01.x, accA[0]);
        accB[0] = fma2(ppB, v01.x, accB[0]);
        accA[1] = fma2(ppA, v01.y, accA[1]);
        accB[1] = fma2(ppB, v01.y, accB[1]);
        accA[2] = fma2(ppA, v23.x, accA[2]);
        accB[2] = fma2(ppB, v23.x, accB[2]);
        accA[3] = fma2(ppA, v23.y, accA[3]);
        accB[3] = fma2(ppB, v23.y, accB[3]);
        accA[4] = fma2(ppA, v45.x, accA[4]);
        accB[4] = fma2(ppB, v45.x, accB[4]);
        accA[5] = fma2(ppA, v45.y, accA[5]);
        accB[5] = fma2(ppB, v45.y, accB[5]);
        accA[6] = fma2(ppA, v67.x, accA[6]);
        accB[6] = fma2(ppB, v67.x, accB[6]);
        accA[7] = fma2(ppA, v67.y, accA[7]);
        accB[7] = fma2(ppB, v67.y, accB[7]);
    }

    int pidx = ((bh * 4 + kq) * 2 + qh) * 128 + t;
    ((ulonglong2*)g_pl)[pidx] = make_ulonglong2(lA, lB);
    ulonglong2* pa = (ulonglong2*)(g_pacc + (size_t)pidx * 16);
    pa[0] = make_ulonglong2(accA[0], accA[1]);
    pa[1] = make_ulonglong2(accA[2], accA[3]);
    pa[2] = make_ulonglong2(accA[4], accA[5]);
    pa[3] = make_ulonglong2(accA[6], accA[7]);
    pa[4] = make_ulonglong2(accB[0], accB[1]);
    pa[5] = make_ulonglong2(accB[2], accB[3]);
    pa[6] = make_ulonglong2(accB[4], accB[5]);
    pa[7] = make_ulonglong2(accB[6], accB[7]);
}

// ---------------- attention pass 2: sum 4 partials, normalize ---------------
__global__ __launch_bounds__(256) void attn_p2_kernel()
{
    int idx = blockIdx.x * 256 + threadIdx.x;
    int bh = idx >> 8;
    int r  = idx & 255;
    int qh = r >> 7;
    int t  = r & 127;
    int b = bh >> 5;
    int h = bh & 31;

    ULL lA = 0ULL, lB = 0ULL;
    ULL cA[8], cB[8];
    #pragma unroll
    for (int j = 0; j < 8; j++) { cA[j] = 0ULL; cB[j] = 0ULL; }

    #pragma unroll
    for (int kq = 0; kq < 4; kq++) {
        int pidx = ((bh * 4 + kq) * 2 + qh) * 128 + t;
        ulonglong2 lp = ((const ulonglong2*)g_pl)[pidx];
        lA = add2(lA, lp.x);
        lB = add2(lB, lp.y);
        const ulonglong2* pa = (const ulonglong2*)(g_pacc + (size_t)pidx * 16);
        ulonglong2 a0 = pa[0], a1 = pa[1], a2 = pa[2], a3 = pa[3];
        ulonglong2 b0 = pa[4], b1 = pa[5], b2 = pa[6], b3 = pa[7];
        cA[0] = add2(cA[0], a0.x); cA[1] = add2(cA[1], a0.y);
        cA[2] = add2(cA[2], a1.x); cA[3] = add2(cA[3], a1.y);
        cA[4] = add2(cA[4], a2.x); cA[5] = add2(cA[5], a2.y);
        cA[6] = add2(cA[6], a3.x); cA[7] = add2(cA[7], a3.y);
        cB[0] = add2(cB[0], b0.x); cB[1] = add2(cB[1], b0.y);
        cB[2] = add2(cB[2], b1.x); cB[3] = add2(cB[3], b1.y);
        cB[4] = add2(cB[4], b2.x); cB[5] = add2(cB[5], b2.y);
        cB[6] = add2(cB[6], b3.x); cB[7] = add2(cB[7], b3.y);
    }

    float LA0, LA1, LB0, LB1;
    unpk(lA, LA0, LA1);
    unpk(lB, LB0, LB1);
    float r0 = 1.f / LA0, r1 = 1.f / LA1, r2 = 1.f / LB0, r3 = 1.f / LB1;

    int q0 = qh * 512 + t;
    float* o0 = g_ctx + ((size_t)b * S_ + q0)       * E_ + h * DK_;
    float* o1 = g_ctx + ((size_t)b * S_ + q0 + 128) * E_ + h * DK_;
    float* o2 = g_ctx + ((size_t)b * S_ + q0 + 256) * E_ + h * DK_;
    float* o3 = g_ctx + ((size_t)b * S_ + q0 + 384) * E_ + h * DK_;

    float xA0[8], xA1[8], xB0[8], xB1[8];
    #pragma unroll
    for (int j = 0; j < 8; j++) { unpk(cA[j], xA0[j], xA1[j]); unpk(cB[j], xB0[j], xB1[j]); }
    float4 w;
    w.x = xA0[0]*r0; w.y = xA0[1]*r0; w.z = xA0[2]*r0; w.w = xA0[3]*r0;
    *(float4*)(o0) = w;
    w.x = xA0[4]*r0; w.y = xA0[5]*r0; w.z = xA0[6]*r0; w.w = xA0[7]*r0;
    *(float4*)(o0 + 4) = w;
    w.x = xA1[0]*r1; w.y = xA1[1]*r1; w.z = xA1[2]*r1; w.w = xA1[3]*r1;
    *(float4*)(o1) = w;
    w.x = xA1[4]*r1; w.y = xA1[5]*r1; w.z = xA1[6]*r1; w.w = xA1[7]*r1;
    *(float4*)(o1 + 4) = w;
    w.x = xB0[0]*r2; w.y = xB0[1]*r2; w.z = xB0[2]*r2; w.w = xB0[3]*r2;
    *(float4*)(o2) = w;
    w.x = xB0[4]*r2; w.y = xB0[5]*r2; w.z = xB0[6]*r2; w.w = xB0[7]*r2;
    *(float4*)(o2 + 4) = w;
    w.x = xB1[0]*r3; w.y = xB1[1]*r3; w.z = xB1[2]*r3; w.w = xB1[3]*r3;
    *(float4*)(o3) = w;
    w.x = xB1[4]*r3; w.y = xB1[5]*r3; w.z = xB1[6]*r3; w.w = xB1[7]*r3;
    *(float4*)(o3 + 4) = w;
}

// ---------------- layernorm: out = LN(a + b) * g + beta  (warp per row) -----
__global__ __launch_bounds__(256) void ln_kernel(
    const float* __restrict__ a, const float* __restrict__ bsrc,
    const float* __restrict__ g, const float* __restrict__ beta,
    float* __restrict__ out)
{
    int row  = (blockIdx.x * 256 + threadIdx.x) >> 5;
    int lane = threadIdx.x & 31;
    size_t off = (size_t)row * E_ + lane * 8;

    const float4* ap = (const float4*)(a + off);
    const float4* bp = (const float4*)(bsrc + off);
    float4 a0 = ap[0], a1 = ap[1], b0 = bp[0], b1 = bp[1];
    float v[8];
    v[0] = a0.x + b0.x; v[1] = a0.y + b0.y; v[2] = a0.z + b0.z; v[3] = a0.w + b0.w;
    v[4] = a1.x + b1.x; v[5] = a1.y + b1.y; v[6] = a1.z + b1.z; v[7] = a1.w + b1.w;

    float s = 0.f, ss = 0.f;
    #pragma unroll
    for (int i = 0; i < 8; i++) { s += v[i]; ss = fmaf(v[i], v[i], ss); }
    #pragma unroll
    for (int o = 16; o > 0; o >>= 1) {
        s  += __shfl_xor_sync(0xFFFFFFFFu, s,  o);
        ss += __shfl_xor_sync(0xFFFFFFFFu, ss, o);
    }
    float mu  = s * (1.f / E_);
    float var = ss * (1.f / E_) - mu * mu;
    float rs  = rsqrtf(var + 1e-5f);

    const float4* gp  = (const float4*)(g    + lane * 8);
    const float4* bep = (const float4*)(beta + lane * 8);
    float4 g0 = gp[0], g1v = gp[1], e0 = bep[0], e1 = bep[1];

    float4 w;
    w.x = (v[0]-mu)*rs*g0.x + e0.x; w.y = (v[1]-mu)*rs*g0.y + e0.y;
    w.z = (v[2]-mu)*rs*g0.z + e0.z; w.w = (v[3]-mu)*rs*g0.w + e0.w;
    *(float4*)(out + off) = w;
    w.x = (v[4]-mu)*rs*g1v.x + e1.x; w.y = (v[5]-mu)*rs*g1v.y + e1.y;
    w.z = (v[6]-mu)*rs*g1v.z + e1.z; w.w = (v[7]-mu)*rs*g1v.w + e1.w;
    *(float4*)(out + off + 4) = w;
}

// ---------------- qf = cos(theta)*cos(h @ w_ip^T + b_ip), warp per row ------
__global__ __launch_bounds__(256) void qf_kernel(
    const float* __restrict__ w_ip, const float* __restrict__ b_ip,
    const float* __restrict__ theta_ffn)
{
    int tid = threadIdx.x;
    int m = blockIdx.x * 8 + (tid >> 5);
    int lane = tid & 31;
    int j = lane >> 2, p = lane & 3;
    const float* hr = g_h + (size_t)m * E_ + p * 64;
    const float* wr = w_ip + (size_t)j * E_ + p * 64;
    ULL acc = 0ULL;
    #pragma unroll
    for (int i = 0; i < 64; i += 8) {
        float4 hA = *(const float4*)(hr + i);
        float4 hB = *(const float4*)(hr + i + 4);
        float4 wA = *(const float4*)(wr + i);
        float4 wB = *(const float4*)(wr + i + 4);
        acc = fma2(pk(hA.x, hA.y), pk(wA.x, wA.y), acc);
        acc = fma2(pk(hA.z, hA.w), pk(wA.z, wA.w), acc);
        acc = fma2(pk(hB.x, hB.y), pk(wB.x, wB.y), acc);
        acc = fma2(pk(hB.z, hB.w), pk(wB.z, wB.w), acc);
    }
    float s0, s1;
    unpk(acc, s0, s1);
    float s = s0 + s1;
    s += __shfl_xor_sync(0xFFFFFFFFu, s, 1);
    s += __shfl_xor_sync(0xFFFFFFFFu, s, 2);
    if (p == 0)
        g_qf[m * NQ_ + j] = __cosf(theta_ffn[j]) * __cosf(s + b_ip[j]);
}

// ---------------- hidden = relu(qf @ w1^T + b1)   (K=8) ---------------------
__global__ __launch_bounds__(256) void hidden_kernel(
    const float* __restrict__ w1, const float* __restrict__ b1)
{
    int m = blockIdx.x >> 2;
    int f = ((blockIdx.x & 3) << 8) + threadIdx.x;
    const float* qr = g_qf + (size_t)m * NQ_;
    const float* wr = w1 + (size_t)f * NQ_;
    float s = b1[f];
    #pragma unroll
    for (int j = 0; j < NQ_; j++)
        s = fmaf(qr[j], wr[j], s);
    g_hidden[(size_t)m * FF_ + f] = fmaxf(s, 0.f);
}

// ---------------- launch ----------------------------------------------------
extern "C" void kernel_launch(void* const* d_in, const int* in_sizes, int n_in,
                              void* d_out, int out_size)
{
    (void)in_sizes; (void)n_in; (void)out_size;

    const float* x          = (const float*)d_in[0];
    const float* theta_attn = (const float*)d_in[1];
    const float* w_in       = (const float*)d_in[2];
    const float* b_in       = (const float*)d_in[3];
    const float* w_out      = (const float*)d_in[4];
    const float* b_out      = (const float*)d_in[5];
    const float* w_comb     = (const float*)d_in[6];
    const float* b_comb     = (const float*)d_in[7];
    const float* g1         = (const float*)d_in[8];
    const float* be1        = (const float*)d_in[9];
    const float* g2         = (const float*)d_in[10];
    const float* be2        = (const float*)d_in[11];
    const float* w_ip       = (const float*)d_in[12];
    const float* b_ip       = (const float*)d_in[13];
    const float* theta_ffn  = (const float*)d_in[14];
    const float* w1         = (const float*)d_in[15];
    const float* b1         = (const float*)d_in[16];
    const float* w2         = (const float*)d_in[17];
    const float* b2         = (const float*)d_in[18];
    float* out = (float*)d_out;

    float *p_qout, *p_qkv, *p_ctx, *p_Wf, *p_bf, *p_tmp, *p_h, *p_hidden;
    cudaGetSymbolAddress((void**)&p_qout,   g_qout);
    cudaGetSymbolAddress((void**)&p_qkv,    g_qkv);
    cudaGetSymbolAddress((void**)&p_ctx,    g_ctx);
    cudaGetSymbolAddress((void**)&p_Wf,     g_Wf);
    cudaGetSymbolAddress((void**)&p_bf,     g_bf);
    cudaGetSymbolAddress((void**)&p_tmp,    g_tmp);
    cudaGetSymbolAddress((void**)&p_h,      g_h);
    cudaGetSymbolAddress((void**)&p_hidden, g_hidden);

    // 1. q_out = cos(x + theta)
    cos_encode_kernel<<<(M_ * E_) / 1024, 256>>>(x, theta_attn);

    // 2. fold w_comb @ w_out
    fold_w_kernel<<<E_, 256>>>(w_comb, w_out, b_out, b_comb);

    // 3. qkv = q_out @ w_in^T + b_in      [4096 x 768]
    {
        dim3 grid((3 * E_) / 64, M_ / 64);
        sgemm64_kernel<<<grid, 256>>>(p_qout, w_in, b_in, p_qkv, M_, 3 * E_, E_);
    }

    // 4a. attention pass 1 (split-K partials)
    {
        dim3 grid(4, 2, B_ * H_);
        attn_p1_kernel<<<grid, 128>>>();
    }
    // 4b. attention pass 2 (sum + normalize) -> ctx
    attn_p2_kernel<<<128, 256>>>();

    // 5. attn_out = ctx @ Wf^T + bf       [4096 x 256]
    {
        dim3 grid(E_ / 64, M_ / 64);
        sgemm64_kernel<<<grid, 256>>>(p_ctx, p_Wf, p_bf, p_tmp, M_, E_, E_);
    }

    // 6. h = LN(x + attn_out) * g1 + be1
    ln_kernel<<<M_ / 8, 256>>>(x, p_tmp, g1, be1, p_h);

    // 7. qf = cos(theta_ffn) * cos(h @ w_ip^T + b_ip)
    qf_kernel<<<M_ / 8, 256>>>(w_ip, b_ip, theta_ffn);

    // 8. hidden = relu(qf @ w1^T + b1)    [4096 x 1024]
    hidden_kernel<<<M_ * 4, 256>>>(w1, b1);

    // 9. ffn_out = hidden @ w2^T + b2     [4096 x 256]
    {
        dim3 grid(E_ / 64, M_ / 64);
        sgemm64_kernel<<<grid, 256>>>(p_hidden, w2, b2, p_tmp, M_, E_, FF_);
    }

    // 10. out = LN(h + ffn_out) * g2 + be2
    ln_kernel<<<M_ / 8, 256>>>(p_h, p_tmp, g2, be2, out);
}

// round 8
// speedup vs baseline: 1.1934x; 1.0890x over previous
#include <cuda_runtime.h>
#include <math.h>
#include <stdint.h>

// Problem constants
#define B_   4
#define S_   1024
#define E_   256
#define H_   32
#define DK_  8
#define NQ_  8
#define FF_  1024
#define M_   (B_ * S_)   // 4096

typedef unsigned long long ULL;

// ---------------- f32x2 packed math helpers (PTX-only on sm_103a) ----------
__device__ __forceinline__ ULL fma2(ULL a, ULL b, ULL c) {
    ULL d; asm("fma.rn.f32x2 %0, %1, %2, %3;" : "=l"(d) : "l"(a), "l"(b), "l"(c)); return d;
}
__device__ __forceinline__ ULL mul2(ULL a, ULL b) {
    ULL d; asm("mul.rn.f32x2 %0, %1, %2;" : "=l"(d) : "l"(a), "l"(b)); return d;
}
__device__ __forceinline__ ULL add2(ULL a, ULL b) {
    ULL d; asm("add.rn.f32x2 %0, %1, %2;" : "=l"(d) : "l"(a), "l"(b)); return d;
}
__device__ __forceinline__ ULL pk(float lo, float hi) {
    ULL r; asm("mov.b64 %0, {%1, %2};" : "=l"(r) : "f"(lo), "f"(hi)); return r;
}
__device__ __forceinline__ void unpk(ULL v, float& lo, float& hi) {
    asm("mov.b64 {%0, %1}, %2;" : "=f"(lo), "=f"(hi) : "l"(v));
}
__device__ __forceinline__ float ex2f_(float x) {
    float y; asm("ex2.approx.f32 %0, %1;" : "=f"(y) : "f"(x)); return y;
}

// ---------------- scratch (device globals; no runtime allocation) ----------
__device__ __align__(16) float g_qout[M_ * E_];
__device__ __align__(16) float g_qkv[M_ * 3 * E_];
__device__ __align__(16) float g_ctx[M_ * E_];
__device__ __align__(16) float g_Wf[E_ * E_];
__device__ __align__(16) float g_bf[E_];
__device__ __align__(16) float g_tmp[M_ * E_];
__device__ __align__(16) float g_h[M_ * E_];
__device__ __align__(16) float g_qf[M_ * NQ_];
__device__ __align__(16) float g_hidden[M_ * FF_];
// split-K attention partials (plain floats; lo/hi combined in pass 1)
// pidx = ((bh*4 + kq)*2 + qh)*128 + t ; queries qh*512 + t + {0,128,256,384}
__device__ __align__(16) float g_plf[131072 * 4];
__device__ __align__(16) float g_paccf[(size_t)131072 * 32];

// ---------------- q_out = cos(x + theta[e % 8]), float4 --------------------
__global__ __launch_bounds__(256) void cos_encode_kernel(
    const float* __restrict__ x, const float* __restrict__ theta)
{
    int i = (blockIdx.x * 256 + threadIdx.x) * 4;
    float4 v = *(const float4*)(x + i);
    int j = i & 7;
    v.x = __cosf(v.x + theta[j + 0]);
    v.y = __cosf(v.y + theta[j + 1]);
    v.z = __cosf(v.z + theta[j + 2]);
    v.w = __cosf(v.w + theta[j + 3]);
    *(float4*)(g_qout + i) = v;
}

// ---------------- fold: Wf = w_comb @ w_out, bf = w_comb@b_out + b_comb -----
__global__ __launch_bounds__(256) void fold_w_kernel(
    const float* __restrict__ w_comb, const float* __restrict__ w_out,
    const float* __restrict__ b_out, const float* __restrict__ b_comb)
{
    int i = blockIdx.x;
    int j = threadIdx.x;
    float s = 0.f;
    #pragma unroll 8
    for (int k = 0; k < E_; k++)
        s = fmaf(w_comb[i * E_ + k], w_out[k * E_ + j], s);
    g_Wf[i * E_ + j] = s;

    __shared__ float red[256];
    red[j] = w_comb[i * E_ + j] * b_out[j];
    __syncthreads();
    #pragma unroll
    for (int off = 128; off > 0; off >>= 1) {
        if (j < off) red[j] += red[j + off];
        __syncthreads();
    }
    if (j == 0) g_bf[i] = red[0] + b_comb[i];
}

// ---------------- f32x2 SGEMM (R5 version): C = A @ Bw^T + bias ------------
// BM=128, BN=64, BK=16, 256 threads, 8x4 microtile.
__global__ __launch_bounds__(256) void sgemm2_kernel(
    const float* __restrict__ A, const float* __restrict__ Bw,
    const float* __restrict__ bias, float* __restrict__ C,
    int M, int N, int K)
{
    __shared__ float As[16][132];
    __shared__ float Bs[16][68];

    int tid = threadIdx.x;
    int bm = blockIdx.y * 128;
    int bn = blockIdx.x * 64;
    int ty = tid >> 4;
    int tx = tid & 15;

    int alr = tid >> 1;
    int alc = (tid & 1) * 8;
    int blr = tid >> 2;
    int blc = (tid & 3) * 4;

    const float* Aptr = A  + (size_t)(bm + alr) * K + alc;
    const float* Bptr = Bw + (size_t)(bn + blr) * K + blc;

    float4 a0 = *(const float4*)(Aptr);
    float4 a1 = *(const float4*)(Aptr + 4);
    float4 b0 = *(const float4*)(Bptr);

    ULL acc[4][4];
    #pragma unroll
    for (int r = 0; r < 4; r++)
        #pragma unroll
        for (int j = 0; j < 4; j++) acc[r][j] = 0ULL;

    for (int k0 = 0; ; k0 += 16) {
        As[alc + 0][alr] = a0.x; As[alc + 1][alr] = a0.y;
        As[alc + 2][alr] = a0.z; As[alc + 3][alr] = a0.w;
        As[alc + 4][alr] = a1.x; As[alc + 5][alr] = a1.y;
        As[alc + 6][alr] = a1.z; As[alc + 7][alr] = a1.w;
        Bs[blc + 0][blr] = b0.x; Bs[blc + 1][blr] = b0.y;
        Bs[blc + 2][blr] = b0.z; Bs[blc + 3][blr] = b0.w;
        __syncthreads();

        bool last = (k0 + 16 >= K);
        if (!last) {
            Aptr += 16; Bptr += 16;
            a0 = *(const float4*)(Aptr);
            a1 = *(const float4*)(Aptr + 4);
            b0 = *(const float4*)(Bptr);
        }

        #pragma unroll
        for (int kk = 0; kk < 16; kk++) {
            ulonglong2 am0 = *(const ulonglong2*)&As[kk][ty * 8];
            ulonglong2 am1 = *(const ulonglong2*)&As[kk][ty * 8 + 4];
            float4 b4 = *(const float4*)&Bs[kk][tx * 4];
            ULL bb0 = pk(b4.x, b4.x), bb1 = pk(b4.y, b4.y);
            ULL bb2 = pk(b4.z, b4.z), bb3 = pk(b4.w, b4.w);
            ULL am[4] = {am0.x, am0.y, am1.x, am1.y};
            #pragma unroll
            for (int r = 0; r < 4; r++) {
                acc[r][0] = fma2(am[r], bb0, acc[r][0]);
                acc[r][1] = fma2(am[r], bb1, acc[r][1]);
                acc[r][2] = fma2(am[r], bb2, acc[r][2]);
                acc[r][3] = fma2(am[r], bb3, acc[r][3]);
            }
        }
        if (last) break;
        __syncthreads();
    }

    int col = bn + tx * 4;
    float4 bb = *(const float4*)(bias + col);
    #pragma unroll
    for (int r = 0; r < 4; r++) {
        float lo0, hi0, lo1, hi1, lo2v, hi2, lo3, hi3;
        unpk(acc[r][0], lo0, hi0);
        unpk(acc[r][1], lo1, hi1);
        unpk(acc[r][2], lo2v, hi2);
        unpk(acc[r][3], lo3, hi3);
        int row0 = bm + ty * 8 + 2 * r;
        *(float4*)(C + (size_t)row0 * N + col) =
            make_float4(lo0 + bb.x, lo1 + bb.y, lo2v + bb.z, lo3 + bb.w);
        *(float4*)(C + (size_t)(row0 + 1) * N + col) =
            make_float4(hi0 + bb.x, hi1 + bb.y, hi2 + bb.z, hi3 + bb.w);
    }
}

// ---------------- attention pass 1: keys-packed, no-max softmax -------------
// grid = (4 key-quarters, 2 query-halves, 128 bh), 128 threads.
// K/V packed across ADJACENT KEY PAIRS in smem (no duplication, 16 KB);
// 4 queries/thread duplicated (q,q) in registers. Halves LDS vs R5.
__global__ __launch_bounds__(128) void attn_p1_kernel()
{
    __shared__ ULL Kp[128 * 8];   // 8 KB: Kp[sp*8+c] = (k_{2sp}[c], k_{2sp+1}[c])
    __shared__ ULL Vp[128 * 8];   // 8 KB

    int kq = blockIdx.x;
    int qh = blockIdx.y;
    int bh = blockIdx.z;
    int b = bh >> 5;
    int h = bh & 31;
    int t = threadIdx.x;
    const float* base = g_qkv + (size_t)b * S_ * (3 * E_) + h * DK_;

    // stage: thread t packs keys (2t, 2t+1)
    {
        const float* ra = base + (size_t)(kq * 256 + 2 * t) * (3 * E_);
        const float* rb = ra + 3 * E_;
        float4 ka0 = *(const float4*)(ra + E_);
        float4 ka1 = *(const float4*)(ra + E_ + 4);
        float4 kb0 = *(const float4*)(rb + E_);
        float4 kb1 = *(const float4*)(rb + E_ + 4);
        ulonglong2* kw = (ulonglong2*)(Kp + t * 8);
        kw[0] = make_ulonglong2(pk(ka0.x, kb0.x), pk(ka0.y, kb0.y));
        kw[1] = make_ulonglong2(pk(ka0.z, kb0.z), pk(ka0.w, kb0.w));
        kw[2] = make_ulonglong2(pk(ka1.x, kb1.x), pk(ka1.y, kb1.y));
        kw[3] = make_ulonglong2(pk(ka1.z, kb1.z), pk(ka1.w, kb1.w));
        float4 va0 = *(const float4*)(ra + 2 * E_);
        float4 va1 = *(const float4*)(ra + 2 * E_ + 4);
        float4 vb0 = *(const float4*)(rb + 2 * E_);
        float4 vb1 = *(const float4*)(rb + 2 * E_ + 4);
        ulonglong2* vw = (ulonglong2*)(Vp + t * 8);
        vw[0] = make_ulonglong2(pk(va0.x, vb0.x), pk(va0.y, vb0.y));
        vw[1] = make_ulonglong2(pk(va0.z, vb0.z), pk(va0.w, vb0.w));
        vw[2] = make_ulonglong2(pk(va1.x, vb1.x), pk(va1.y, vb1.y));
        vw[3] = make_ulonglong2(pk(va1.z, vb1.z), pk(va1.w, vb1.w));
    }
    __syncthreads();

    const float qscale = 0.35355339059327373f * 1.4426950408889634f; // log2e/sqrt(8)

    // 4 queries duplicated in regs: qd[i][c] = (q_i[c]*s, q_i[c]*s)
    ULL qd[4][8];
    #pragma unroll
    for (int i = 0; i < 4; i++) {
        const float* r = base + (size_t)(qh * 512 + t + i * 128) * (3 * E_);
        float4 q0 = *(const float4*)(r);
        float4 q1 = *(const float4*)(r + 4);
        float s;
        s = q0.x * qscale; qd[i][0] = pk(s, s);
        s = q0.y * qscale; qd[i][1] = pk(s, s);
        s = q0.z * qscale; qd[i][2] = pk(s, s);
        s = q0.w * qscale; qd[i][3] = pk(s, s);
        s = q1.x * qscale; qd[i][4] = pk(s, s);
        s = q1.y * qscale; qd[i][5] = pk(s, s);
        s = q1.z * qscale; qd[i][6] = pk(s, s);
        s = q1.w * qscale; qd[i][7] = pk(s, s);
    }

    ULL l[4] = {0ULL, 0ULL, 0ULL, 0ULL};
    ULL acc[4][8];
    #pragma unroll
    for (int i = 0; i < 4; i++)
        #pragma unroll
        for (int c = 0; c < 8; c++) acc[i][c] = 0ULL;

    #pragma unroll 1
    for (int sp = 0; sp < 128; sp++) {
        const ulonglong2* kr = (const ulonglong2*)(Kp + sp * 8);
        ulonglong2 k01 = kr[0], k23 = kr[1], k45 = kr[2], k67 = kr[3];

        // 4 independent packed dot chains -> (d_even, d_odd) per query
        ULL t0 = mul2(qd[0][0], k01.x);
        ULL t1 = mul2(qd[1][0], k01.x);
        ULL t2 = mul2(qd[2][0], k01.x);
        ULL t3 = mul2(qd[3][0], k01.x);
        t0 = fma2(qd[0][1], k01.y, t0);
        t1 = fma2(qd[1][1], k01.y, t1);
        t2 = fma2(qd[2][1], k01.y, t2);
        t3 = fma2(qd[3][1], k01.y, t3);
        t0 = fma2(qd[0][2], k23.x, t0);
        t1 = fma2(qd[1][2], k23.x, t1);
        t2 = fma2(qd[2][2], k23.x, t2);
        t3 = fma2(qd[3][2], k23.x, t3);
        t0 = fma2(qd[0][3], k23.y, t0);
        t1 = fma2(qd[1][3], k23.y, t1);
        t2 = fma2(qd[2][3], k23.y, t2);
        t3 = fma2(qd[3][3], k23.y, t3);
        t0 = fma2(qd[0][4], k45.x, t0);
        t1 = fma2(qd[1][4], k45.x, t1);
        t2 = fma2(qd[2][4], k45.x, t2);
        t3 = fma2(qd[3][4], k45.x, t3);
        t0 = fma2(qd[0][5], k45.y, t0);
        t1 = fma2(qd[1][5], k45.y, t1);
        t2 = fma2(qd[2][5], k45.y, t2);
        t3 = fma2(qd[3][5], k45.y, t3);
        t0 = fma2(qd[0][6], k67.x, t0);
        t1 = fma2(qd[1][6], k67.x, t1);
        t2 = fma2(qd[2][6], k67.x, t2);
        t3 = fma2(qd[3][6], k67.x, t3);
        t0 = fma2(qd[0][7], k67.y, t0);
        t1 = fma2(qd[1][7], k67.y, t1);
        t2 = fma2(qd[2][7], k67.y, t2);
        t3 = fma2(qd[3][7], k67.y, t3);

        float d0, d1;
        unpk(t0, d0, d1);
        ULL pp0 = pk(ex2f_(d0), ex2f_(d1));
        unpk(t1, d0, d1);
        ULL pp1 = pk(ex2f_(d0), ex2f_(d1));
        unpk(t2, d0, d1);
        ULL pp2 = pk(ex2f_(d0), ex2f_(d1));
        unpk(t3, d0, d1);
        ULL pp3 = pk(ex2f_(d0), ex2f_(d1));
        l[0] = add2(l[0], pp0);
        l[1] = add2(l[1], pp1);
        l[2] = add2(l[2], pp2);
        l[3] = add2(l[3], pp3);

        const ulonglong2* vr = (const ulonglong2*)(Vp + sp * 8);
        ulonglong2 v01 = vr[0], v23 = vr[1], v45 = vr[2], v67 = vr[3];
        acc[0][0] = fma2(pp0, v01.x, acc[0][0]);
        acc[1][0] = fma2(pp1, v01.x, acc[1][0]);
        acc[2][0] = fma2(pp2, v01.x, acc[2][0]);
        acc[3][0] = fma2(pp3, v01.x, acc[3][0]);
        acc[0][1] = fma2(pp0, v01.y, acc[0][1]);
        acc[1][1] = fma2(pp1, v01.y, acc[1][1]);
        acc[2][1] = fma2(pp2, v01.y, acc[2][1]);
        acc[3][1] = fma2(pp3, v01.y, acc[3][1]);
        acc[0][2] = fma2(pp0, v23.x, acc[0][2]);
        acc[1][2] = fma2(pp1, v23.x, acc[1][2]);
        acc[2][2] = fma2(pp2, v23.x, acc[2][2]);
        acc[3][2] = fma2(pp3, v23.x, acc[3][2]);
        acc[0][3] = fma2(pp0, v23.y, acc[0][3]);
        acc[1][3] = fma2(pp1, v23.y, acc[1][3]);
        acc[2][3] = fma2(pp2, v23.y, acc[2][3]);
        acc[3][3] = fma2(pp3, v23.y, acc[3][3]);
        acc[0][4] = fma2(pp0, v45.x, acc[0][4]);
        acc[1][4] = fma2(pp1, v45.x, acc[1][4]);
        acc[2][4] = fma2(pp2, v45.x, acc[2][4]);
        acc[3][4] = fma2(pp3, v45.x, acc[3][4]);
        acc[0][5] = fma2(pp0, v45.y, acc[0][5]);
        acc[1][5] = fma2(pp1, v45.y, acc[1][5]);
        acc[2][5] = fma2(pp2, v45.y, acc[2][5]);
        acc[3][5] = fma2(pp3, v45.y, acc[3][5]);
        acc[0][6] = fma2(pp0, v67.x, acc[0][6]);
        acc[1][6] = fma2(pp1, v67.x, acc[1][6]);
        acc[2][6] = fma2(pp2, v67.x, acc[2][6]);
        acc[3][6] = fma2(pp3, v67.x, acc[3][6]);
        acc[0][7] = fma2(pp0, v67.y, acc[0][7]);
        acc[1][7] = fma2(pp1, v67.y, acc[1][7]);
        acc[2][7] = fma2(pp2, v67.y, acc[2][7]);
        acc[3][7] = fma2(pp3, v67.y, acc[3][7]);
    }

    // fold packed even/odd halves and write float partials
    int pidx = ((bh * 4 + kq) * 2 + qh) * 128 + t;
    {
        float lo, hi;
        float lv[4];
        #pragma unroll
        for (int i = 0; i < 4; i++) { unpk(l[i], lo, hi); lv[i] = lo + hi; }
        *(float4*)(g_plf + pidx * 4) = make_float4(lv[0], lv[1], lv[2], lv[3]);
        float* pa = g_paccf + (size_t)pidx * 32;
        #pragma unroll
        for (int i = 0; i < 4; i++) {
            float av[8];
            #pragma unroll
            for (int c = 0; c < 8; c++) { unpk(acc[i][c], lo, hi); av[c] = lo + hi; }
            *(float4*)(pa + i * 8)     = make_float4(av[0], av[1], av[2], av[3]);
            *(float4*)(pa + i * 8 + 4) = make_float4(av[4], av[5], av[6], av[7]);
        }
    }
}

// ---------------- attention pass 2: sum 4 partials, normalize ---------------
__global__ __launch_bounds__(256) void attn_p2_kernel()
{
    int idx = blockIdx.x * 256 + threadIdx.x;   // 32768 threads
    int bh = idx >> 8;
    int r  = idx & 255;
    int qh = r >> 7;
    int t  = r & 127;
    int b = bh >> 5;
    int h = bh & 31;

    float L[4] = {0.f, 0.f, 0.f, 0.f};
    float c[4][8];
    #pragma unroll
    for (int i = 0; i < 4; i++)
        #pragma unroll
        for (int j = 0; j < 8; j++) c[i][j] = 0.f;

    #pragma unroll
    for (int kq = 0; kq < 4; kq++) {
        int pidx = ((bh * 4 + kq) * 2 + qh) * 128 + t;
        float4 lv = *(const float4*)(g_plf + pidx * 4);
        L[0] += lv.x; L[1] += lv.y; L[2] += lv.z; L[3] += lv.w;
        const float4* pa = (const float4*)(g_paccf + (size_t)pidx * 32);
        #pragma unroll
        for (int i = 0; i < 4; i++) {
            float4 a0 = pa[2 * i], a1 = pa[2 * i + 1];
            c[i][0] += a0.x; c[i][1] += a0.y; c[i][2] += a0.z; c[i][3] += a0.w;
            c[i][4] += a1.x; c[i][5] += a1.y; c[i][6] += a1.z; c[i][7] += a1.w;
        }
    }

    #pragma unroll
    for (int i = 0; i < 4; i++) {
        float rr = 1.f / L[i];
        int q = qh * 512 + t + i * 128;
        float* o = g_ctx + ((size_t)b * S_ + q) * E_ + h * DK_;
        *(float4*)(o)     = make_float4(c[i][0] * rr, c[i][1] * rr, c[i][2] * rr, c[i][3] * rr);
        *(float4*)(o + 4) = make_float4(c[i][4] * rr, c[i][5] * rr, c[i][6] * rr, c[i][7] * rr);
    }
}

// ---------------- layernorm: out = LN(a + b) * g + beta  (warp per row) -----
__global__ __launch_bounds__(256) void ln_kernel(
    const float* __restrict__ a, const float* __restrict__ bsrc,
    const float* __restrict__ g, const float* __restrict__ beta,
    float* __restrict__ out)
{
    int row  = (blockIdx.x * 256 + threadIdx.x) >> 5;
    int lane = threadIdx.x & 31;
    size_t off = (size_t)row * E_ + lane * 8;

    const float4* ap = (const float4*)(a + off);
    const float4* bp = (const float4*)(bsrc + off);
    float4 a0 = ap[0], a1 = ap[1], b0 = bp[0], b1 = bp[1];
    float v[8];
    v[0] = a0.x + b0.x; v[1] = a0.y + b0.y; v[2] = a0.z + b0.z; v[3] = a0.w + b0.w;
    v[4] = a1.x + b1.x; v[5] = a1.y + b1.y; v[6] = a1.z + b1.z; v[7] = a1.w + b1.w;

    float s = 0.f, ss = 0.f;
    #pragma unroll
    for (int i = 0; i < 8; i++) { s += v[i]; ss = fmaf(v[i], v[i], ss); }
    #pragma unroll
    for (int o = 16; o > 0; o >>= 1) {
        s  += __shfl_xor_sync(0xFFFFFFFFu, s,  o);
        ss += __shfl_xor_sync(0xFFFFFFFFu, ss, o);
    }
    float mu  = s * (1.f / E_);
    float var = ss * (1.f / E_) - mu * mu;
    float rs  = rsqrtf(var + 1e-5f);

    const float4* gp  = (const float4*)(g    + lane * 8);
    const float4* bep = (const float4*)(beta + lane * 8);
    float4 g0 = gp[0], g1v = gp[1], e0 = bep[0], e1 = bep[1];

    float4 w;
    w.x = (v[0]-mu)*rs*g0.x + e0.x; w.y = (v[1]-mu)*rs*g0.y + e0.y;
    w.z = (v[2]-mu)*rs*g0.z + e0.z; w.w = (v[3]-mu)*rs*g0.w + e0.w;
    *(float4*)(out + off) = w;
    w.x = (v[4]-mu)*rs*g1v.x + e1.x; w.y = (v[5]-mu)*rs*g1v.y + e1.y;
    w.z = (v[6]-mu)*rs*g1v.z + e1.z; w.w = (v[7]-mu)*rs*g1v.w + e1.w;
    *(float4*)(out + off + 4) = w;
}

// ---------------- qf = cos(theta)*cos(h @ w_ip^T + b_ip), warp per row ------
__global__ __launch_bounds__(256) void qf_kernel(
    const float* __restrict__ w_ip, const float* __restrict__ b_ip,
    const float* __restrict__ theta_ffn)
{
    int tid = threadIdx.x;
    int m = blockIdx.x * 8 + (tid >> 5);
    int lane = tid & 31;
    int j = lane >> 2, p = lane & 3;
    const float* hr = g_h + (size_t)m * E_ + p * 64;
    const float* wr = w_ip + (size_t)j * E_ + p * 64;
    ULL acc = 0ULL;
    #pragma unroll
    for (int i = 0; i < 64; i += 8) {
        float4 hA = *(const float4*)(hr + i);
        float4 hB = *(const float4*)(hr + i + 4);
        float4 wA = *(const float4*)(wr + i);
        float4 wB = *(const float4*)(wr + i + 4);
        acc = fma2(pk(hA.x, hA.y), pk(wA.x, wA.y), acc);
        acc = fma2(pk(hA.z, hA.w), pk(wA.z, wA.w), acc);
        acc = fma2(pk(hB.x, hB.y), pk(wB.x, wB.y), acc);
        acc = fma2(pk(hB.z, hB.w), pk(wB.z, wB.w), acc);
    }
    float s0, s1;
    unpk(acc, s0, s1);
    float s = s0 + s1;
    s += __shfl_xor_sync(0xFFFFFFFFu, s, 1);
    s += __shfl_xor_sync(0xFFFFFFFFu, s, 2);
    if (p == 0)
        g_qf[m * NQ_ + j] = __cosf(theta_ffn[j]) * __cosf(s + b_ip[j]);
}

// ---------------- hidden = relu(qf @ w1^T + b1)   (K=8) ---------------------
__global__ __launch_bounds__(256) void hidden_kernel(
    const float* __restrict__ w1, const float* __restrict__ b1)
{
    int m = blockIdx.x >> 2;
    int f = ((blockIdx.x & 3) << 8) + threadIdx.x;
    const float* qr = g_qf + (size_t)m * NQ_;
    const float* wr = w1 + (size_t)f * NQ_;
    float s = b1[f];
    #pragma unroll
    for (int j = 0; j < NQ_; j++)
        s = fmaf(qr[j], wr[j], s);
    g_hidden[(size_t)m * FF_ + f] = fmaxf(s, 0.f);
}

// ---------------- launch ----------------------------------------------------
extern "C" void kernel_launch(void* const* d_in, const int* in_sizes, int n_in,
                              void* d_out, int out_size)
{
    (void)in_sizes; (void)n_in; (void)out_size;

    const float* x          = (const float*)d_in[0];
    const float* theta_attn = (const float*)d_in[1];
    const float* w_in       = (const float*)d_in[2];
    const float* b_in       = (const float*)d_in[3];
    const float* w_out      = (const float*)d_in[4];
    const float* b_out      = (const float*)d_in[5];
    const float* w_comb     = (const float*)d_in[6];
    const float* b_comb     = (const float*)d_in[7];
    const float* g1         = (const float*)d_in[8];
    const float* be1        = (const float*)d_in[9];
    const float* g2         = (const float*)d_in[10];
    const float* be2        = (const float*)d_in[11];
    const float* w_ip       = (const float*)d_in[12];
    const float* b_ip       = (const float*)d_in[13];
    const float* theta_ffn  = (const float*)d_in[14];
    const float* w1         = (const float*)d_in[15];
    const float* b1         = (const float*)d_in[16];
    const float* w2         = (const float*)d_in[17];
    const float* b2         = (const float*)d_in[18];
    float* out = (float*)d_out;

    float *p_qout, *p_qkv, *p_ctx, *p_Wf, *p_bf, *p_tmp, *p_h, *p_hidden;
    cudaGetSymbolAddress((void**)&p_qout,   g_qout);
    cudaGetSymbolAddress((void**)&p_qkv,    g_qkv);
    cudaGetSymbolAddress((void**)&p_ctx,    g_ctx);
    cudaGetSymbolAddress((void**)&p_Wf,     g_Wf);
    cudaGetSymbolAddress((void**)&p_bf,     g_bf);
    cudaGetSymbolAddress((void**)&p_tmp,    g_tmp);
    cudaGetSymbolAddress((void**)&p_h,      g_h);
    cudaGetSymbolAddress((void**)&p_hidden, g_hidden);

    // 1. q_out = cos(x + theta)
    cos_encode_kernel<<<(M_ * E_) / 1024, 256>>>(x, theta_attn);

    // 2. fold w_comb @ w_out
    fold_w_kernel<<<E_, 256>>>(w_comb, w_out, b_out, b_comb);

    // 3. qkv = q_out @ w_in^T + b_in      [4096 x 768]
    {
        dim3 grid((3 * E_) / 64, M_ / 128);
        sgemm2_kernel<<<grid, 256>>>(p_qout, w_in, b_in, p_qkv, M_, 3 * E_, E_);
    }

    // 4a. attention pass 1 (split-K partials, keys-packed)
    {
        dim3 grid(4, 2, B_ * H_);
        attn_p1_kernel<<<grid, 128>>>();
    }
    // 4b. attention pass 2 (sum + normalize) -> ctx
    attn_p2_kernel<<<128, 256>>>();

    // 5. attn_out = ctx @ Wf^T + bf       [4096 x 256]
    {
        dim3 grid(E_ / 64, M_ / 128);
        sgemm2_kernel<<<grid, 256>>>(p_ctx, p_Wf, p_bf, p_tmp, M_, E_, E_);
    }

    // 6. h = LN(x + attn_out) * g1 + be1
    ln_kernel<<<M_ / 8, 256>>>(x, p_tmp, g1, be1, p_h);

    // 7. qf = cos(theta_ffn) * cos(h @ w_ip^T + b_ip)
    qf_kernel<<<M_ / 8, 256>>>(w_ip, b_ip, theta_ffn);

    // 8. hidden = relu(qf @ w1^T + b1)    [4096 x 1024]
    hidden_kernel<<<M_ * 4, 256>>>(w1, b1);

    // 9. ffn_out = hidden @ w2^T + b2     [4096 x 256]
    {
        dim3 grid(E_ / 64, M_ / 128);
        sgemm2_kernel<<<grid, 256>>>(p_hidden, w2, b2, p_tmp, M_, E_, FF_);
    }

    // 10. out = LN(h + ffn_out) * g2 + be2
    ln_kernel<<<M_ / 8, 256>>>(p_h, p_tmp, g2, be2, out);
}